// round 4
// baseline (speedup 1.0000x reference)
#include <cuda_runtime.h>
#include <cuda_bf16.h>
#include <cstdint>
#include <cstddef>

#define BB 128
#define TT 64
#define HH 256
#define VV 128
#define G3H 768

// ---------------- persistent scratch ----------------
__device__ float g_xp [BB*TT*G3H];     // input projections (both layers, reused)
__device__ float g_seq[BB*TT*HH];      // layer-0 output
__device__ float g_enc[BB*TT*HH];      // layer-1 output (encoder)
__device__ float g_Wa [BB*TT*HH];
__device__ float g_Ua [BB*TT*HH];
__device__ float g_ctx[BB*TT*HH];
__device__ float g_hbuf[2][BB*HH];     // double-buffered hidden state
__device__ unsigned g_bcnt[32*32];     // per-group barrier counters (128B apart)
__device__ unsigned g_bph [32*32];     // per-group barrier phases

// ---------------- helpers ----------------
union F2U { float2 f; unsigned long long u; };

__device__ __forceinline__ float2 ffma2(float2 a, float2 b, float2 c) {
    F2U A, B, C, D; A.f = a; B.f = b; C.f = c;
    asm("fma.rn.f32x2 %0, %1, %2, %3;" : "=l"(D.u) : "l"(A.u), "l"(B.u), "l"(C.u));
    return D.f;
}

__device__ __forceinline__ float4 ffma4(float a, float4 b, float4 c) {
    float2 p = ffma2(make_float2(a, a), make_float2(b.x, b.y), make_float2(c.x, c.y));
    float2 q = ffma2(make_float2(a, a), make_float2(b.z, b.w), make_float2(c.z, c.w));
    return make_float4(p.x, p.y, q.x, q.y);
}

__device__ __forceinline__ float tanha(float x) {
    float y; asm("tanh.approx.f32 %0, %1;" : "=f"(y) : "f"(x)); return y;
}

__device__ __forceinline__ float sigm(float x) {
    return 1.f / (1.f + __expf(-x));
}

// ---------------- GEMM: C[m,n] = sum_k A[m,k]*W[n,k] (+bias | +=C) ----------------
// BM=128 BN=64 BK=16, 256 threads, 8x4 per thread, f32x2 packed FMA.
// gather != null: A row m is A + gather[m]*lda (embedding lookup fused).
__global__ void __launch_bounds__(256)
gemm_k(const float* __restrict__ A, int lda, const int* __restrict__ gather,
       const float* __restrict__ W, int ldw,
       const float* __restrict__ bias,
       float* __restrict__ C, int ldc, int K, int accumulate)
{
    __shared__ float As[16 * 132];
    __shared__ float Bs[16 * 68];

    const int tid = threadIdx.x;
    const int tx = tid & 15;           // n
    const int ty = tid >> 4;           // m
    const int mbase = blockIdx.x * 128;
    const int nbase = blockIdx.y * 64;

    float4 acc[8];
#pragma unroll
    for (int i = 0; i < 8; ++i) acc[i] = make_float4(0.f, 0.f, 0.f, 0.f);

    const int ktiles = K >> 4;
    for (int kt = 0; kt < ktiles; ++kt) {
        // A tile: 128 x 16 -> As[k][m]
#pragma unroll
        for (int l = 0; l < 2; ++l) {
            int idx = tid + l * 256;           // 0..511
            int r = idx >> 2, c4 = idx & 3;
            int m = mbase + r;
            const float* arow = A + (size_t)(gather ? gather[m] : m) * lda;
            float4 v = __ldg((const float4*)(arow + kt * 16 + c4 * 4));
            As[(c4 * 4 + 0) * 132 + r] = v.x;
            As[(c4 * 4 + 1) * 132 + r] = v.y;
            As[(c4 * 4 + 2) * 132 + r] = v.z;
            As[(c4 * 4 + 3) * 132 + r] = v.w;
        }
        // W tile: 64 x 16 -> Bs[k][n]
        {
            int n = tid >> 2, c4 = tid & 3;
            float4 v = __ldg((const float4*)(W + (size_t)(nbase + n) * ldw + kt * 16 + c4 * 4));
            Bs[(c4 * 4 + 0) * 68 + n] = v.x;
            Bs[(c4 * 4 + 1) * 68 + n] = v.y;
            Bs[(c4 * 4 + 2) * 68 + n] = v.z;
            Bs[(c4 * 4 + 3) * 68 + n] = v.w;
        }
        __syncthreads();
#pragma unroll
        for (int k = 0; k < 16; ++k) {
            float4 a0 = *(const float4*)&As[k * 132 + ty * 8];
            float4 a1 = *(const float4*)&As[k * 132 + ty * 8 + 4];
            float4 b4 = *(const float4*)&Bs[k * 68 + tx * 4];
            acc[0] = ffma4(a0.x, b4, acc[0]);
            acc[1] = ffma4(a0.y, b4, acc[1]);
            acc[2] = ffma4(a0.z, b4, acc[2]);
            acc[3] = ffma4(a0.w, b4, acc[3]);
            acc[4] = ffma4(a1.x, b4, acc[4]);
            acc[5] = ffma4(a1.y, b4, acc[5]);
            acc[6] = ffma4(a1.z, b4, acc[6]);
            acc[7] = ffma4(a1.w, b4, acc[7]);
        }
        __syncthreads();
    }

    const int n0 = nbase + tx * 4;
    float4 bv = make_float4(0.f, 0.f, 0.f, 0.f);
    if (bias) bv = *(const float4*)&bias[n0];
#pragma unroll
    for (int mi = 0; mi < 8; ++mi) {
        int m = mbase + ty * 8 + mi;
        float4* cp = (float4*)&C[(size_t)m * ldc + n0];
        float4 o = acc[mi];
        if (accumulate) {
            float4 old = *cp;
            o.x += old.x; o.y += old.y; o.z += old.z; o.w += old.w;
        } else {
            o.x += bv.x; o.y += bv.y; o.z += bv.z; o.w += bv.w;
        }
        *cp = o;
    }
}

// ---------------- GRU scan (persistent, 32 groups x 4 CTAs) ----------------
__device__ __forceinline__ void group_barrier(int gslot, unsigned& sense) {
    __threadfence();
    __syncthreads();
    if (threadIdx.x == 0) {
        unsigned arr = atomicAdd(&g_bcnt[gslot], 1u);
        if (arr == 3u) {
            g_bcnt[gslot] = 0u;
            __threadfence();
            *(volatile unsigned*)&g_bph[gslot] = sense ^ 1u;
        } else {
            while (*(volatile unsigned*)&g_bph[gslot] == sense) { __nanosleep(64); }
        }
        sense ^= 1u;
    }
    __syncthreads();
}

__global__ void __launch_bounds__(256, 1)
scan_k(const float* __restrict__ xp, const float* __restrict__ w_hh,
       const float* __restrict__ b_hh, float* __restrict__ seq,
       float* __restrict__ hlast)
{
    __shared__ float sh_h[4][256];
    const int g = blockIdx.x >> 2;         // batch group: batches 4g..4g+3
    const int c = blockIdx.x & 3;          // j slice: [c*64, c*64+64)
    const int gslot = g * 32;
    const int tid = threadIdx.x;
    const int j = tid >> 2;                // 0..63
    const int kq = tid & 3;                // k quarter / batch lane
    const int jg = c * 64 + j;

    const float4* w0 = (const float4*)(w_hh + (size_t)(0 * 256 + jg) * 256);
    const float4* w1 = (const float4*)(w_hh + (size_t)(1 * 256 + jg) * 256);
    const float4* w2 = (const float4*)(w_hh + (size_t)(2 * 256 + jg) * 256);
    const float bh0 = b_hh[jg], bh1 = b_hh[256 + jg], bh2 = b_hh[512 + jg];
    const int b0 = g * 4;

    unsigned sense = 0;
    if (tid == 0) sense = *(volatile unsigned*)&g_bph[gslot];

    for (int t = 0; t < TT; ++t) {
        // stage h_{t-1} (4 batches x 256) into smem; L1-bypassing load (cross-SM data)
        if (t == 0) {
            ((float4*)sh_h)[tid] = make_float4(0.f, 0.f, 0.f, 0.f);
        } else {
            const float4* src = (const float4*)(g_hbuf[(t - 1) & 1] + (size_t)b0 * 256);
            ((float4*)sh_h)[tid] = __ldcg(src + tid);
        }
        __syncthreads();

        float a0[4] = {0.f, 0.f, 0.f, 0.f};
        float a1[4] = {0.f, 0.f, 0.f, 0.f};
        float a2[4] = {0.f, 0.f, 0.f, 0.f};
#pragma unroll 4
        for (int i = 0; i < 16; ++i) {
            const int f4 = i * 4 + kq;          // interleaved k for conflict-free LDS
            float4 wv0 = __ldg(w0 + f4);        // L1-resident across steps
            float4 wv1 = __ldg(w1 + f4);
            float4 wv2 = __ldg(w2 + f4);
#pragma unroll
            for (int b = 0; b < 4; ++b) {
                float4 hv = *(const float4*)&sh_h[b][f4 * 4];
                a0[b] = fmaf(wv0.x, hv.x, fmaf(wv0.y, hv.y, fmaf(wv0.z, hv.z, fmaf(wv0.w, hv.w, a0[b]))));
                a1[b] = fmaf(wv1.x, hv.x, fmaf(wv1.y, hv.y, fmaf(wv1.z, hv.z, fmaf(wv1.w, hv.w, a1[b]))));
                a2[b] = fmaf(wv2.x, hv.x, fmaf(wv2.y, hv.y, fmaf(wv2.z, hv.z, fmaf(wv2.w, hv.w, a2[b]))));
            }
        }
        // reduce the 4 k-quarters (adjacent lanes)
#pragma unroll
        for (int b = 0; b < 4; ++b) {
            a0[b] += __shfl_xor_sync(0xffffffffu, a0[b], 1);
            a0[b] += __shfl_xor_sync(0xffffffffu, a0[b], 2);
            a1[b] += __shfl_xor_sync(0xffffffffu, a1[b], 1);
            a1[b] += __shfl_xor_sync(0xffffffffu, a1[b], 2);
            a2[b] += __shfl_xor_sync(0xffffffffu, a2[b], 1);
            a2[b] += __shfl_xor_sync(0xffffffffu, a2[b], 2);
        }
        // lane kq finishes batch b=kq for this j
        {
            const int b = kq;
            const int m = (b0 + b) * TT + t;
            const float hr = a0[b] + bh0;
            const float hz = a1[b] + bh1;
            const float hn = a2[b] + bh2;
            const float* xr_p = xp + (size_t)m * G3H;
            const float xr = __ldcg(xr_p + jg);
            const float xz = __ldcg(xr_p + 256 + jg);
            const float xn = __ldcg(xr_p + 512 + jg);
            const float r = sigm(xr + hr);
            const float z = sigm(xz + hz);
            const float n = tanhf(xn + r * hn);
            const float hprev = sh_h[b][jg];
            const float hnew = (1.f - z) * n + z * hprev;
            __stcg(g_hbuf[t & 1] + (size_t)(b0 + b) * 256 + jg, hnew);
            seq[(size_t)m * 256 + jg] = hnew;
            if (hlast != nullptr && t == TT - 1)
                hlast[(size_t)(b0 + b) * 256 + jg] = hnew;
        }
        group_barrier(gslot, sense);
    }
}

// ---------------- attention (CTA per batch) ----------------
// smem: WA[64][260] (swizzled wa, later enc plain), UA[64][260], E[64][68], V[256]
#define AT_SMEM_FLOATS (2 * 64 * 260 + 64 * 68 + 256)
#define AT_SMEM_BYTES  (AT_SMEM_FLOATS * 4)

__global__ void __launch_bounds__(256, 1)
attn_k(const float* __restrict__ Wa, const float* __restrict__ Ua,
       const float* __restrict__ enc, const float* __restrict__ va,
       float* __restrict__ ctx)
{
    extern __shared__ float sm[];
    float* WA = sm;
    float* UA = sm + 64 * 260;
    float* ES = sm + 2 * 64 * 260;
    float* VS = ES + 64 * 68;

    const int b = blockIdx.x;
    const int tid = threadIdx.x;
    const float* waB = Wa + (size_t)b * 64 * 256;
    const float* uaB = Ua + (size_t)b * 64 * 256;

    for (int idx = tid; idx < 4096; idx += 256) {
        int k = idx >> 6, h4 = idx & 63;
        float4 w4 = __ldg((const float4*)waB + idx);
        *(float4*)&WA[k * 260 + ((h4 ^ (k & 7)) << 2)] = w4;   // xor swizzle
        float4 u4 = __ldg((const float4*)uaB + idx);
        *(float4*)&UA[k * 260 + (h4 << 2)] = u4;
    }
    if (tid < 64) *(float4*)&VS[tid * 4] = __ldg((const float4*)va + tid);
    __syncthreads();

    // energy: thread covers 2 t x 8 k (k strided by 8 -> k&7 == kq matches swizzle)
    const int tq = tid >> 3, kq = tid & 7;
    const int t0 = tq * 2;
    float e0[8], e1[8];
#pragma unroll
    for (int i = 0; i < 8; ++i) { e0[i] = 0.f; e1[i] = 0.f; }

    for (int h4 = 0; h4 < 64; ++h4) {
        float4 v4 = *(const float4*)&VS[h4 * 4];
        float4 uA = *(const float4*)&UA[t0 * 260 + h4 * 4];
        float4 uB = *(const float4*)&UA[(t0 + 1) * 260 + h4 * 4];
#pragma unroll
        for (int i = 0; i < 8; ++i) {
            int k = i * 8 + kq;
            float4 w4 = *(const float4*)&WA[k * 260 + ((h4 ^ kq) << 2)];
            e0[i] += tanha(w4.x + uA.x) * v4.x + tanha(w4.y + uA.y) * v4.y
                   + tanha(w4.z + uA.z) * v4.z + tanha(w4.w + uA.w) * v4.w;
            e1[i] += tanha(w4.x + uB.x) * v4.x + tanha(w4.y + uB.y) * v4.y
                   + tanha(w4.z + uB.z) * v4.z + tanha(w4.w + uB.w) * v4.w;
        }
    }
#pragma unroll
    for (int i = 0; i < 8; ++i) {
        ES[t0 * 68 + i * 8 + kq] = e0[i];
        ES[(t0 + 1) * 68 + i * 8 + kq] = e1[i];
    }
    __syncthreads();

    // reload enc into WA (plain layout, stride 260)
    const float* encB = enc + (size_t)b * 64 * 256;
    for (int idx = tid; idx < 4096; idx += 256) {
        int k = idx >> 6, h4 = idx & 63;
        *(float4*)&WA[k * 260 + (h4 << 2)] = __ldg((const float4*)encB + idx);
    }
    __syncthreads();

    // softmax over k (one thread per row t)
    if (tid < 64) {
        float* er = &ES[tid * 68];
        float mx = -1e30f;
        for (int k = 0; k < 64; ++k) mx = fmaxf(mx, er[k]);
        float s = 0.f;
        for (int k = 0; k < 64; ++k) { float e = __expf(er[k] - mx); er[k] = e; s += e; }
        float inv = 1.f / s;
        for (int k = 0; k < 64; ++k) er[k] *= inv;
    }
    __syncthreads();

    // ctx[t][h] = sum_k alpha[t][k] * enc[k][h] ; thread covers 4 t x 16 h-floats
    const int tq2 = tid >> 4, hq = tid & 15;
    const int tb = tq2 * 4;
    float4 cacc[4][4];
#pragma unroll
    for (int dt = 0; dt < 4; ++dt)
#pragma unroll
        for (int jj = 0; jj < 4; ++jj) cacc[dt][jj] = make_float4(0.f, 0.f, 0.f, 0.f);

    for (int k = 0; k < 64; ++k) {
        float al[4];
#pragma unroll
        for (int dt = 0; dt < 4; ++dt) al[dt] = ES[(tb + dt) * 68 + k];
        float4 ev[4];
#pragma unroll
        for (int jj = 0; jj < 4; ++jj) ev[jj] = *(const float4*)&WA[k * 260 + hq * 16 + jj * 4];
#pragma unroll
        for (int dt = 0; dt < 4; ++dt)
#pragma unroll
            for (int jj = 0; jj < 4; ++jj) cacc[dt][jj] = ffma4(al[dt], ev[jj], cacc[dt][jj]);
    }
#pragma unroll
    for (int dt = 0; dt < 4; ++dt)
#pragma unroll
        for (int jj = 0; jj < 4; ++jj)
            *(float4*)&ctx[(size_t)(b * 64 + tb + dt) * 256 + hq * 16 + jj * 4] = cacc[dt][jj];
}

// ---------------- launch ----------------
extern "C" void kernel_launch(void* const* d_in, const int* in_sizes, int n_in,
                              void* d_out, int out_size)
{
    const int*   x     = (const int*)  d_in[0];
    const float* embed = (const float*)d_in[1];
    const float* w_ih0 = (const float*)d_in[2];
    const float* w_hh0 = (const float*)d_in[3];
    const float* b_ih0 = (const float*)d_in[4];
    const float* b_hh0 = (const float*)d_in[5];
    const float* w_ih1 = (const float*)d_in[6];
    const float* w_hh1 = (const float*)d_in[7];
    const float* b_ih1 = (const float*)d_in[8];
    const float* b_hh1 = (const float*)d_in[9];
    const float* W_a   = (const float*)d_in[10];
    const float* U_a   = (const float*)d_in[11];
    const float* v_a   = (const float*)d_in[12];
    const float* fc_W  = (const float*)d_in[13];
    const float* fc_b  = (const float*)d_in[14];

    float* out = (float*)d_out;                 // logits (B,T,V) then h_last (B,H)
    float* hlast = out + (size_t)BB * TT * VV;

    float *xp, *seq, *enc, *wa, *ua, *ctx;
    cudaGetSymbolAddress((void**)&xp,  g_xp);
    cudaGetSymbolAddress((void**)&seq, g_seq);
    cudaGetSymbolAddress((void**)&enc, g_enc);
    cudaGetSymbolAddress((void**)&wa,  g_Wa);
    cudaGetSymbolAddress((void**)&ua,  g_Ua);
    cudaGetSymbolAddress((void**)&ctx, g_ctx);

    cudaFuncSetAttribute(attn_k, cudaFuncAttributeMaxDynamicSharedMemorySize, AT_SMEM_BYTES);

    const int M = BB * TT;  // 8192

    // 1. xp0 = embed[x] @ w_ih0^T + b_ih0    (gather fused)
    gemm_k<<<dim3(M / 128, G3H / 64), 256>>>(embed, HH, x, w_ih0, HH, b_ih0, xp, G3H, HH, 0);
    // 2. scan layer 0
    scan_k<<<128, 256>>>(xp, w_hh0, b_hh0, seq, nullptr);
    // 3. xp1 = seq @ w_ih1^T + b_ih1
    gemm_k<<<dim3(M / 128, G3H / 64), 256>>>(seq, HH, nullptr, w_ih1, HH, b_ih1, xp, G3H, HH, 0);
    // 4. scan layer 1 -> enc, h_last
    scan_k<<<128, 256>>>(xp, w_hh1, b_hh1, enc, hlast);
    // 5/6. attention projections
    gemm_k<<<dim3(M / 128, HH / 64), 256>>>(enc, HH, nullptr, W_a, HH, nullptr, wa, HH, HH, 0);
    gemm_k<<<dim3(M / 128, HH / 64), 256>>>(enc, HH, nullptr, U_a, HH, nullptr, ua, HH, HH, 0);
    // 7. attention -> ctx
    attn_k<<<BB, 256, AT_SMEM_BYTES>>>(wa, ua, enc, v_a, ctx);
    // 8/9. logits = enc @ fcW[:, :H]^T + b  ;  += ctx @ fcW[:, H:]^T
    gemm_k<<<dim3(M / 128, VV / 64), 256>>>(enc, HH, nullptr, fc_W, 2 * HH, fc_b, out, VV, HH, 0);
    gemm_k<<<dim3(M / 128, VV / 64), 256>>>(ctx, HH, nullptr, fc_W + HH, 2 * HH, nullptr, out, VV, HH, 1);
}

// round 5
// speedup vs baseline: 1.0004x; 1.0004x over previous
#include <cuda_runtime.h>
#include <cuda_bf16.h>
#include <cstdint>
#include <cstddef>

#define BB 128
#define TT 64
#define HH 256
#define VV 128
#define G3H 768

// ---------------- persistent scratch ----------------
__device__ float g_xp [BB*TT*G3H];     // input projections (both layers, reused)
__device__ float g_seq[BB*TT*HH];      // layer-0 output
__device__ float g_enc[BB*TT*HH];      // layer-1 output (encoder)
__device__ float g_Wa [BB*TT*HH];
__device__ float g_Ua [BB*TT*HH];
__device__ float g_ctx[BB*TT*HH];
__device__ float g_hbuf[2][BB*HH];     // double-buffered hidden state
__device__ unsigned g_bcnt[32*32];     // per-group barrier counters (128B apart)
__device__ unsigned g_bph [32*32];     // per-group barrier phases

// ---------------- helpers ----------------
union F2U { float2 f; unsigned long long u; };

__device__ __forceinline__ float2 ffma2(float2 a, float2 b, float2 c) {
    F2U A, B, C, D; A.f = a; B.f = b; C.f = c;
    asm("fma.rn.f32x2 %0, %1, %2, %3;" : "=l"(D.u) : "l"(A.u), "l"(B.u), "l"(C.u));
    return D.f;
}

__device__ __forceinline__ float4 ffma4(float a, float4 b, float4 c) {
    float2 p = ffma2(make_float2(a, a), make_float2(b.x, b.y), make_float2(c.x, c.y));
    float2 q = ffma2(make_float2(a, a), make_float2(b.z, b.w), make_float2(c.z, c.w));
    return make_float4(p.x, p.y, q.x, q.y);
}

__device__ __forceinline__ float tanha(float x) {
    float y; asm("tanh.approx.f32 %0, %1;" : "=f"(y) : "f"(x)); return y;
}

__device__ __forceinline__ float sigm(float x) {
    return 1.f / (1.f + __expf(-x));
}

// ---------------- GEMM: C[m,n] = sum_k A[m,k]*W[n,k] (+bias | +=C) ----------------
// BM=128 BN=64 BK=16, 256 threads, 8x4 per thread, f32x2 packed FMA.
// gather != null: A row m is A + gather[m]*lda (embedding lookup fused).
__global__ void __launch_bounds__(256)
gemm_k(const float* __restrict__ A, int lda, const int* __restrict__ gather,
       const float* __restrict__ W, int ldw,
       const float* __restrict__ bias,
       float* __restrict__ C, int ldc, int K, int accumulate)
{
    __shared__ float As[16 * 132];
    __shared__ float Bs[16 * 68];

    const int tid = threadIdx.x;
    const int tx = tid & 15;           // n
    const int ty = tid >> 4;           // m
    const int mbase = blockIdx.x * 128;
    const int nbase = blockIdx.y * 64;

    float4 acc[8];
#pragma unroll
    for (int i = 0; i < 8; ++i) acc[i] = make_float4(0.f, 0.f, 0.f, 0.f);

    const int ktiles = K >> 4;
    for (int kt = 0; kt < ktiles; ++kt) {
        // A tile: 128 x 16 -> As[k][m]
#pragma unroll
        for (int l = 0; l < 2; ++l) {
            int idx = tid + l * 256;           // 0..511
            int r = idx >> 2, c4 = idx & 3;
            int m = mbase + r;
            const float* arow = A + (size_t)(gather ? gather[m] : m) * lda;
            float4 v = __ldg((const float4*)(arow + kt * 16 + c4 * 4));
            As[(c4 * 4 + 0) * 132 + r] = v.x;
            As[(c4 * 4 + 1) * 132 + r] = v.y;
            As[(c4 * 4 + 2) * 132 + r] = v.z;
            As[(c4 * 4 + 3) * 132 + r] = v.w;
        }
        // W tile: 64 x 16 -> Bs[k][n]
        {
            int n = tid >> 2, c4 = tid & 3;
            float4 v = __ldg((const float4*)(W + (size_t)(nbase + n) * ldw + kt * 16 + c4 * 4));
            Bs[(c4 * 4 + 0) * 68 + n] = v.x;
            Bs[(c4 * 4 + 1) * 68 + n] = v.y;
            Bs[(c4 * 4 + 2) * 68 + n] = v.z;
            Bs[(c4 * 4 + 3) * 68 + n] = v.w;
        }
        __syncthreads();
#pragma unroll
        for (int k = 0; k < 16; ++k) {
            float4 a0 = *(const float4*)&As[k * 132 + ty * 8];
            float4 a1 = *(const float4*)&As[k * 132 + ty * 8 + 4];
            float4 b4 = *(const float4*)&Bs[k * 68 + tx * 4];
            acc[0] = ffma4(a0.x, b4, acc[0]);
            acc[1] = ffma4(a0.y, b4, acc[1]);
            acc[2] = ffma4(a0.z, b4, acc[2]);
            acc[3] = ffma4(a0.w, b4, acc[3]);
            acc[4] = ffma4(a1.x, b4, acc[4]);
            acc[5] = ffma4(a1.y, b4, acc[5]);
            acc[6] = ffma4(a1.z, b4, acc[6]);
            acc[7] = ffma4(a1.w, b4, acc[7]);
        }
        __syncthreads();
    }

    const int n0 = nbase + tx * 4;
    float4 bv = make_float4(0.f, 0.f, 0.f, 0.f);
    if (bias) bv = *(const float4*)&bias[n0];
#pragma unroll
    for (int mi = 0; mi < 8; ++mi) {
        int m = mbase + ty * 8 + mi;
        float4* cp = (float4*)&C[(size_t)m * ldc + n0];
        float4 o = acc[mi];
        if (accumulate) {
            float4 old = *cp;
            o.x += old.x; o.y += old.y; o.z += old.z; o.w += old.w;
        } else {
            o.x += bv.x; o.y += bv.y; o.z += bv.z; o.w += bv.w;
        }
        *cp = o;
    }
}

// ---------------- GRU scan (persistent, 32 groups x 4 CTAs) ----------------
__device__ __forceinline__ void group_barrier(int gslot, unsigned& sense) {
    __threadfence();
    __syncthreads();
    if (threadIdx.x == 0) {
        unsigned arr = atomicAdd(&g_bcnt[gslot], 1u);
        if (arr == 3u) {
            g_bcnt[gslot] = 0u;
            __threadfence();
            *(volatile unsigned*)&g_bph[gslot] = sense ^ 1u;
        } else {
            while (*(volatile unsigned*)&g_bph[gslot] == sense) { __nanosleep(64); }
        }
        sense ^= 1u;
    }
    __syncthreads();
}

__global__ void __launch_bounds__(256, 1)
scan_k(const float* __restrict__ xp, const float* __restrict__ w_hh,
       const float* __restrict__ b_hh, float* __restrict__ seq,
       float* __restrict__ hlast)
{
    __shared__ float sh_h[4][256];
    const int g = blockIdx.x >> 2;         // batch group: batches 4g..4g+3
    const int c = blockIdx.x & 3;          // j slice: [c*64, c*64+64)
    const int gslot = g * 32;
    const int tid = threadIdx.x;
    const int j = tid >> 2;                // 0..63
    const int kq = tid & 3;                // k quarter / batch lane
    const int jg = c * 64 + j;

    const float4* w0 = (const float4*)(w_hh + (size_t)(0 * 256 + jg) * 256);
    const float4* w1 = (const float4*)(w_hh + (size_t)(1 * 256 + jg) * 256);
    const float4* w2 = (const float4*)(w_hh + (size_t)(2 * 256 + jg) * 256);
    const float bh0 = b_hh[jg], bh1 = b_hh[256 + jg], bh2 = b_hh[512 + jg];
    const int b0 = g * 4;

    unsigned sense = 0;
    if (tid == 0) sense = *(volatile unsigned*)&g_bph[gslot];

    for (int t = 0; t < TT; ++t) {
        // stage h_{t-1} (4 batches x 256) into smem; L1-bypassing load (cross-SM data)
        if (t == 0) {
            ((float4*)sh_h)[tid] = make_float4(0.f, 0.f, 0.f, 0.f);
        } else {
            const float4* src = (const float4*)(g_hbuf[(t - 1) & 1] + (size_t)b0 * 256);
            ((float4*)sh_h)[tid] = __ldcg(src + tid);
        }
        __syncthreads();

        float a0[4] = {0.f, 0.f, 0.f, 0.f};
        float a1[4] = {0.f, 0.f, 0.f, 0.f};
        float a2[4] = {0.f, 0.f, 0.f, 0.f};
#pragma unroll 4
        for (int i = 0; i < 16; ++i) {
            const int f4 = i * 4 + kq;          // interleaved k for conflict-free LDS
            float4 wv0 = __ldg(w0 + f4);        // L1-resident across steps
            float4 wv1 = __ldg(w1 + f4);
            float4 wv2 = __ldg(w2 + f4);
#pragma unroll
            for (int b = 0; b < 4; ++b) {
                float4 hv = *(const float4*)&sh_h[b][f4 * 4];
                a0[b] = fmaf(wv0.x, hv.x, fmaf(wv0.y, hv.y, fmaf(wv0.z, hv.z, fmaf(wv0.w, hv.w, a0[b]))));
                a1[b] = fmaf(wv1.x, hv.x, fmaf(wv1.y, hv.y, fmaf(wv1.z, hv.z, fmaf(wv1.w, hv.w, a1[b]))));
                a2[b] = fmaf(wv2.x, hv.x, fmaf(wv2.y, hv.y, fmaf(wv2.z, hv.z, fmaf(wv2.w, hv.w, a2[b]))));
            }
        }
        // reduce the 4 k-quarters (adjacent lanes)
#pragma unroll
        for (int b = 0; b < 4; ++b) {
            a0[b] += __shfl_xor_sync(0xffffffffu, a0[b], 1);
            a0[b] += __shfl_xor_sync(0xffffffffu, a0[b], 2);
            a1[b] += __shfl_xor_sync(0xffffffffu, a1[b], 1);
            a1[b] += __shfl_xor_sync(0xffffffffu, a1[b], 2);
            a2[b] += __shfl_xor_sync(0xffffffffu, a2[b], 1);
            a2[b] += __shfl_xor_sync(0xffffffffu, a2[b], 2);
        }
        // lane kq finishes batch b=kq for this j
        {
            const int b = kq;
            const int m = (b0 + b) * TT + t;
            const float hr = a0[b] + bh0;
            const float hz = a1[b] + bh1;
            const float hn = a2[b] + bh2;
            const float* xr_p = xp + (size_t)m * G3H;
            const float xr = __ldcg(xr_p + jg);
            const float xz = __ldcg(xr_p + 256 + jg);
            const float xn = __ldcg(xr_p + 512 + jg);
            const float r = sigm(xr + hr);
            const float z = sigm(xz + hz);
            const float n = tanhf(xn + r * hn);
            const float hprev = sh_h[b][jg];
            const float hnew = (1.f - z) * n + z * hprev;
            __stcg(g_hbuf[t & 1] + (size_t)(b0 + b) * 256 + jg, hnew);
            seq[(size_t)m * 256 + jg] = hnew;
            if (hlast != nullptr && t == TT - 1)
                hlast[(size_t)(b0 + b) * 256 + jg] = hnew;
        }
        group_barrier(gslot, sense);
    }
}

// ---------------- attention (CTA per batch) ----------------
// smem: WA[64][260] (swizzled wa, later enc plain), UA[64][260], E[64][68], V[256]
#define AT_SMEM_FLOATS (2 * 64 * 260 + 64 * 68 + 256)
#define AT_SMEM_BYTES  (AT_SMEM_FLOATS * 4)

__global__ void __launch_bounds__(256, 1)
attn_k(const float* __restrict__ Wa, const float* __restrict__ Ua,
       const float* __restrict__ enc, const float* __restrict__ va,
       float* __restrict__ ctx)
{
    extern __shared__ float sm[];
    float* WA = sm;
    float* UA = sm + 64 * 260;
    float* ES = sm + 2 * 64 * 260;
    float* VS = ES + 64 * 68;

    const int b = blockIdx.x;
    const int tid = threadIdx.x;
    const float* waB = Wa + (size_t)b * 64 * 256;
    const float* uaB = Ua + (size_t)b * 64 * 256;

    for (int idx = tid; idx < 4096; idx += 256) {
        int k = idx >> 6, h4 = idx & 63;
        float4 w4 = __ldg((const float4*)waB + idx);
        *(float4*)&WA[k * 260 + ((h4 ^ (k & 7)) << 2)] = w4;   // xor swizzle
        float4 u4 = __ldg((const float4*)uaB + idx);
        *(float4*)&UA[k * 260 + (h4 << 2)] = u4;
    }
    if (tid < 64) *(float4*)&VS[tid * 4] = __ldg((const float4*)va + tid);
    __syncthreads();

    // energy: thread covers 2 t x 8 k (k strided by 8 -> k&7 == kq matches swizzle)
    const int tq = tid >> 3, kq = tid & 7;
    const int t0 = tq * 2;
    float e0[8], e1[8];
#pragma unroll
    for (int i = 0; i < 8; ++i) { e0[i] = 0.f; e1[i] = 0.f; }

    for (int h4 = 0; h4 < 64; ++h4) {
        float4 v4 = *(const float4*)&VS[h4 * 4];
        float4 uA = *(const float4*)&UA[t0 * 260 + h4 * 4];
        float4 uB = *(const float4*)&UA[(t0 + 1) * 260 + h4 * 4];
#pragma unroll
        for (int i = 0; i < 8; ++i) {
            int k = i * 8 + kq;
            float4 w4 = *(const float4*)&WA[k * 260 + ((h4 ^ kq) << 2)];
            e0[i] += tanha(w4.x + uA.x) * v4.x + tanha(w4.y + uA.y) * v4.y
                   + tanha(w4.z + uA.z) * v4.z + tanha(w4.w + uA.w) * v4.w;
            e1[i] += tanha(w4.x + uB.x) * v4.x + tanha(w4.y + uB.y) * v4.y
                   + tanha(w4.z + uB.z) * v4.z + tanha(w4.w + uB.w) * v4.w;
        }
    }
#pragma unroll
    for (int i = 0; i < 8; ++i) {
        ES[t0 * 68 + i * 8 + kq] = e0[i];
        ES[(t0 + 1) * 68 + i * 8 + kq] = e1[i];
    }
    __syncthreads();

    // reload enc into WA (plain layout, stride 260)
    const float* encB = enc + (size_t)b * 64 * 256;
    for (int idx = tid; idx < 4096; idx += 256) {
        int k = idx >> 6, h4 = idx & 63;
        *(float4*)&WA[k * 260 + (h4 << 2)] = __ldg((const float4*)encB + idx);
    }
    __syncthreads();

    // softmax over k (one thread per row t)
    if (tid < 64) {
        float* er = &ES[tid * 68];
        float mx = -1e30f;
        for (int k = 0; k < 64; ++k) mx = fmaxf(mx, er[k]);
        float s = 0.f;
        for (int k = 0; k < 64; ++k) { float e = __expf(er[k] - mx); er[k] = e; s += e; }
        float inv = 1.f / s;
        for (int k = 0; k < 64; ++k) er[k] *= inv;
    }
    __syncthreads();

    // ctx[t][h] = sum_k alpha[t][k] * enc[k][h] ; thread covers 4 t x 16 h-floats
    const int tq2 = tid >> 4, hq = tid & 15;
    const int tb = tq2 * 4;
    float4 cacc[4][4];
#pragma unroll
    for (int dt = 0; dt < 4; ++dt)
#pragma unroll
        for (int jj = 0; jj < 4; ++jj) cacc[dt][jj] = make_float4(0.f, 0.f, 0.f, 0.f);

    for (int k = 0; k < 64; ++k) {
        float al[4];
#pragma unroll
        for (int dt = 0; dt < 4; ++dt) al[dt] = ES[(tb + dt) * 68 + k];
        float4 ev[4];
#pragma unroll
        for (int jj = 0; jj < 4; ++jj) ev[jj] = *(const float4*)&WA[k * 260 + hq * 16 + jj * 4];
#pragma unroll
        for (int dt = 0; dt < 4; ++dt)
#pragma unroll
            for (int jj = 0; jj < 4; ++jj) cacc[dt][jj] = ffma4(al[dt], ev[jj], cacc[dt][jj]);
    }
#pragma unroll
    for (int dt = 0; dt < 4; ++dt)
#pragma unroll
        for (int jj = 0; jj < 4; ++jj)
            *(float4*)&ctx[(size_t)(b * 64 + tb + dt) * 256 + hq * 16 + jj * 4] = cacc[dt][jj];
}

// ---------------- launch ----------------
extern "C" void kernel_launch(void* const* d_in, const int* in_sizes, int n_in,
                              void* d_out, int out_size)
{
    const int*   x     = (const int*)  d_in[0];
    const float* embed = (const float*)d_in[1];
    const float* w_ih0 = (const float*)d_in[2];
    const float* w_hh0 = (const float*)d_in[3];
    const float* b_ih0 = (const float*)d_in[4];
    const float* b_hh0 = (const float*)d_in[5];
    const float* w_ih1 = (const float*)d_in[6];
    const float* w_hh1 = (const float*)d_in[7];
    const float* b_ih1 = (const float*)d_in[8];
    const float* b_hh1 = (const float*)d_in[9];
    const float* W_a   = (const float*)d_in[10];
    const float* U_a   = (const float*)d_in[11];
    const float* v_a   = (const float*)d_in[12];
    const float* fc_W  = (const float*)d_in[13];
    const float* fc_b  = (const float*)d_in[14];

    float* out = (float*)d_out;                 // logits (B,T,V) then h_last (B,H)
    float* hlast = out + (size_t)BB * TT * VV;

    float *xp, *seq, *enc, *wa, *ua, *ctx;
    cudaGetSymbolAddress((void**)&xp,  g_xp);
    cudaGetSymbolAddress((void**)&seq, g_seq);
    cudaGetSymbolAddress((void**)&enc, g_enc);
    cudaGetSymbolAddress((void**)&wa,  g_Wa);
    cudaGetSymbolAddress((void**)&ua,  g_Ua);
    cudaGetSymbolAddress((void**)&ctx, g_ctx);

    cudaFuncSetAttribute(attn_k, cudaFuncAttributeMaxDynamicSharedMemorySize, AT_SMEM_BYTES);

    const int M = BB * TT;  // 8192

    // 1. xp0 = embed[x] @ w_ih0^T + b_ih0    (gather fused)
    gemm_k<<<dim3(M / 128, G3H / 64), 256>>>(embed, HH, x, w_ih0, HH, b_ih0, xp, G3H, HH, 0);
    // 2. scan layer 0
    scan_k<<<128, 256>>>(xp, w_hh0, b_hh0, seq, nullptr);
    // 3. xp1 = seq @ w_ih1^T + b_ih1
    gemm_k<<<dim3(M / 128, G3H / 64), 256>>>(seq, HH, nullptr, w_ih1, HH, b_ih1, xp, G3H, HH, 0);
    // 4. scan layer 1 -> enc, h_last
    scan_k<<<128, 256>>>(xp, w_hh1, b_hh1, enc, hlast);
    // 5/6. attention projections
    gemm_k<<<dim3(M / 128, HH / 64), 256>>>(enc, HH, nullptr, W_a, HH, nullptr, wa, HH, HH, 0);
    gemm_k<<<dim3(M / 128, HH / 64), 256>>>(enc, HH, nullptr, U_a, HH, nullptr, ua, HH, HH, 0);
    // 7. attention -> ctx
    attn_k<<<BB, 256, AT_SMEM_BYTES>>>(wa, ua, enc, v_a, ctx);
    // 8/9. logits = enc @ fcW[:, :H]^T + b  ;  += ctx @ fcW[:, H:]^T
    gemm_k<<<dim3(M / 128, VV / 64), 256>>>(enc, HH, nullptr, fc_W, 2 * HH, fc_b, out, VV, HH, 0);
    gemm_k<<<dim3(M / 128, VV / 64), 256>>>(ctx, HH, nullptr, fc_W + HH, 2 * HH, nullptr, out, VV, HH, 1);
}

// round 6
// speedup vs baseline: 1.4259x; 1.4254x over previous
#include <cuda_runtime.h>
#include <cuda_bf16.h>
#include <cstdint>
#include <cstddef>

#define BB 128
#define TT 64
#define HH 256
#define VV 128
#define G3H 768

// ---------------- persistent scratch ----------------
__device__ float g_xp [BB*TT*G3H];     // input projections (both layers, reused)
__device__ float g_seq[BB*TT*HH];      // layer-0 output
__device__ float g_enc[BB*TT*HH];      // layer-1 output (encoder)
__device__ float g_Wa [BB*TT*HH];
__device__ float g_Ua [BB*TT*HH];
__device__ float g_ctx[BB*TT*HH];

// ---------------- helpers ----------------
union F2U { float2 f; unsigned long long u; };

__device__ __forceinline__ float2 ffma2(float2 a, float2 b, float2 c) {
    F2U A, B, C, D; A.f = a; B.f = b; C.f = c;
    asm("fma.rn.f32x2 %0, %1, %2, %3;" : "=l"(D.u) : "l"(A.u), "l"(B.u), "l"(C.u));
    return D.f;
}

__device__ __forceinline__ float4 ffma4(float a, float4 b, float4 c) {
    float2 p = ffma2(make_float2(a, a), make_float2(b.x, b.y), make_float2(c.x, c.y));
    float2 q = ffma2(make_float2(a, a), make_float2(b.z, b.w), make_float2(c.z, c.w));
    return make_float4(p.x, p.y, q.x, q.y);
}

__device__ __forceinline__ float tanha(float x) {
    float y; asm("tanh.approx.f32 %0, %1;" : "=f"(y) : "f"(x)); return y;
}

__device__ __forceinline__ float sigm(float x) {
    return 1.f / (1.f + __expf(-x));
}

__device__ __forceinline__ uint32_t smem_u32(const void* p) {
    uint32_t a;
    asm("{ .reg .u64 t; cvta.to.shared.u64 t, %1; cvt.u32.u64 %0, t; }" : "=r"(a) : "l"(p));
    return a;
}

#define MBARRIER_INIT(addr, cnt) \
    asm volatile("mbarrier.init.shared.b64 [%0], %1;" :: "r"(addr), "r"(cnt) : "memory")

#define MBARRIER_EXPECT_TX(addr, tx) \
    asm volatile("mbarrier.arrive.expect_tx.shared.b64 _, [%0], %1;" :: "r"(addr), "r"(tx) : "memory")

#define MBARRIER_WAIT_PARITY(addr, par) do {                                        \
    uint32_t _m = (addr); uint32_t _p = (par); uint32_t _done;                      \
    asm volatile("{\n\t.reg .pred p;\n\t"                                           \
        "mbarrier.try_wait.parity.acquire.cta.shared::cta.b64 p, [%1], %2;\n\t"     \
        "selp.b32 %0, 1, 0, p;\n\t}"                                                \
        : "=r"(_done) : "r"(_m), "r"(_p) : "memory");                               \
    if (!_done) {                                                                   \
        asm volatile("{\n\t.reg .pred P1;\n\t"                                      \
            "WL_%=:\n\t"                                                            \
            "mbarrier.try_wait.parity.acquire.cta.shared::cta.b64 P1, [%0], %1, 0x989680;\n\t" \
            "@P1 bra.uni WD_%=;\n\t"                                                \
            "bra.uni WL_%=;\n\t"                                                    \
            "WD_%=:\n\t}" :: "r"(_m), "r"(_p) : "memory");                          \
    }                                                                               \
} while (0)

#define ST_ASYNC_B32(raddr, uval, rmbar) \
    asm volatile("st.async.shared::cluster.mbarrier::complete_tx::bytes.b32 [%0], %1, [%2];" \
        :: "r"(raddr), "r"(uval), "r"(rmbar) : "memory")

#define MAPA_U32(dst, laddr, rank) \
    asm("mapa.shared::cluster.u32 %0, %1, %2;" : "=r"(dst) : "r"(laddr), "r"(rank))

#define CLUSTER_SYNC() do {                                              \
    asm volatile("barrier.cluster.arrive.aligned;" ::: "memory");        \
    asm volatile("barrier.cluster.wait.aligned;" ::: "memory");          \
} while (0)

// ---------------- GEMM: C[m,n] = sum_k A[m,k]*W[n,k] (+bias | +=C) ----------------
// BM=128 BN=64 BK=16, 256 threads, 8x4 per thread, f32x2 FMA, register-staged
// k-tile pipelining. gather != null: A row m is A + gather[m]*lda.
__global__ void __launch_bounds__(256)
gemm_k(const float* __restrict__ A, int lda, const int* __restrict__ gather,
       const float* __restrict__ W, int ldw,
       const float* __restrict__ bias,
       float* __restrict__ C, int ldc, int K, int accumulate)
{
    __shared__ float As[16 * 132];
    __shared__ float Bs[16 * 68];

    const int tid = threadIdx.x;
    const int tx = tid & 15;           // n
    const int ty = tid >> 4;           // m
    const int mbase = blockIdx.x * 128;
    const int nbase = blockIdx.y * 64;

    // hoisted load pointers
    const int ra = tid >> 2;           // A rows: ra and ra+64
    const int c4 = tid & 3;            // float4 column within 16-wide k-tile
    const int m0 = mbase + ra;
    const int m1 = mbase + ra + 64;
    const float* arow0 = A + (size_t)(gather ? gather[m0] : m0) * lda;
    const float* arow1 = A + (size_t)(gather ? gather[m1] : m1) * lda;
    const float* wrow  = W + (size_t)(nbase + ra) * ldw;

    float4 acc[8];
#pragma unroll
    for (int i = 0; i < 8; ++i) acc[i] = make_float4(0.f, 0.f, 0.f, 0.f);

    const int ktiles = K >> 4;
    float4 Av0 = __ldg((const float4*)(arow0 + c4 * 4));
    float4 Av1 = __ldg((const float4*)(arow1 + c4 * 4));
    float4 Bv  = __ldg((const float4*)(wrow  + c4 * 4));

    for (int kt = 0; kt < ktiles; ++kt) {
        // regs -> smem (transposed)
        As[(c4 * 4 + 0) * 132 + ra]      = Av0.x;
        As[(c4 * 4 + 1) * 132 + ra]      = Av0.y;
        As[(c4 * 4 + 2) * 132 + ra]      = Av0.z;
        As[(c4 * 4 + 3) * 132 + ra]      = Av0.w;
        As[(c4 * 4 + 0) * 132 + ra + 64] = Av1.x;
        As[(c4 * 4 + 1) * 132 + ra + 64] = Av1.y;
        As[(c4 * 4 + 2) * 132 + ra + 64] = Av1.z;
        As[(c4 * 4 + 3) * 132 + ra + 64] = Av1.w;
        Bs[(c4 * 4 + 0) * 68 + ra] = Bv.x;
        Bs[(c4 * 4 + 1) * 68 + ra] = Bv.y;
        Bs[(c4 * 4 + 2) * 68 + ra] = Bv.z;
        Bs[(c4 * 4 + 3) * 68 + ra] = Bv.w;
        __syncthreads();

        if (kt + 1 < ktiles) {            // prefetch next tile while computing
            Av0 = __ldg((const float4*)(arow0 + (kt + 1) * 16 + c4 * 4));
            Av1 = __ldg((const float4*)(arow1 + (kt + 1) * 16 + c4 * 4));
            Bv  = __ldg((const float4*)(wrow  + (kt + 1) * 16 + c4 * 4));
        }

#pragma unroll
        for (int k = 0; k < 16; ++k) {
            float4 a0 = *(const float4*)&As[k * 132 + ty * 8];
            float4 a1 = *(const float4*)&As[k * 132 + ty * 8 + 4];
            float4 b4 = *(const float4*)&Bs[k * 68 + tx * 4];
            acc[0] = ffma4(a0.x, b4, acc[0]);
            acc[1] = ffma4(a0.y, b4, acc[1]);
            acc[2] = ffma4(a0.z, b4, acc[2]);
            acc[3] = ffma4(a0.w, b4, acc[3]);
            acc[4] = ffma4(a1.x, b4, acc[4]);
            acc[5] = ffma4(a1.y, b4, acc[5]);
            acc[6] = ffma4(a1.z, b4, acc[6]);
            acc[7] = ffma4(a1.w, b4, acc[7]);
        }
        __syncthreads();
    }

    const int n0 = nbase + tx * 4;
    float4 bv = make_float4(0.f, 0.f, 0.f, 0.f);
    if (bias) bv = *(const float4*)&bias[n0];
#pragma unroll
    for (int mi = 0; mi < 8; ++mi) {
        int m = mbase + ty * 8 + mi;
        float4* cp = (float4*)&C[(size_t)m * ldc + n0];
        float4 o = acc[mi];
        if (accumulate) {
            float4 old = *cp;
            o.x += old.x; o.y += old.y; o.z += old.z; o.w += old.w;
        } else {
            o.x += bv.x; o.y += bv.y; o.z += bv.z; o.w += bv.w;
        }
        *cp = o;
    }
}

// ---------------- GRU scan: 32 clusters x 4 CTAs, DSMEM h exchange ----------------
// CTA (cluster rank c) owns j-slice [64c, 64c+64) for 4 batches; its 192x256
// w_hh slice (196KB) stays L1-resident — NO gpu-scope fences anywhere in the loop.
// h exchange: every thread st.async's its h value into all 4 CTAs' smem buffer
// (double-buffered by step parity) with mbarrier complete_tx accounting.
__global__ void __launch_bounds__(256, 1) __cluster_dims__(4, 1, 1)
scan_k(const float* __restrict__ xp, const float* __restrict__ w_hh,
       const float* __restrict__ b_hh, float* __restrict__ seq,
       float* __restrict__ hlast)
{
    __shared__ __align__(16) float hbuf[2][4][256];       // 8KB, [parity][b][j]
    __shared__ __align__(8) unsigned long long mbar[2];

    const int g   = blockIdx.x >> 2;
    const int tid = threadIdx.x;
    const int j   = tid >> 2;                 // 0..63
    const int kq  = tid & 3;                  // k-quarter == local batch lane
    uint32_t rank;
    asm("mov.u32 %0, %%cluster_ctarank;" : "=r"(rank));
    const int jg = (int)rank * 64 + j;
    const int b0 = g * 4;

    const float4* w0 = (const float4*)(w_hh + (size_t)(0 * 256 + jg) * 256);
    const float4* w1 = (const float4*)(w_hh + (size_t)(1 * 256 + jg) * 256);
    const float4* w2 = (const float4*)(w_hh + (size_t)(2 * 256 + jg) * 256);
    const float bh0 = b_hh[jg], bh1 = b_hh[256 + jg], bh2 = b_hh[512 + jg];

    const uint32_t mb0  = smem_u32(&mbar[0]);
    const uint32_t myh  = smem_u32(&hbuf[0][kq][jg]);   // where MY value lives
    uint32_t rh[4], rm[4];
#pragma unroll
    for (int r = 0; r < 4; ++r) { MAPA_U32(rh[r], myh, r); MAPA_U32(rm[r], mb0, r); }

    if (tid == 0) { MBARRIER_INIT(mb0, 1); MBARRIER_INIT(mb0 + 8, 1); }
    __syncthreads();
    CLUSTER_SYNC();                       // all mbars live before any st.async
    if (tid == 0) {                       // open phase 0 of both barriers
        MBARRIER_EXPECT_TX(mb0, 4096);
        MBARRIER_EXPECT_TX(mb0 + 8, 4096);
    }

    const float* xpb = xp + (size_t)(b0 + kq) * TT * G3H;
    float hprev = 0.f;
    int ph0 = 0, ph1 = 0;

    for (int t = 0; t < TT; ++t) {
        // prefetch xp for this (b, t) — latency hidden under wait+compute
        const float* xr_p = xpb + (size_t)t * G3H;
        const float xr = __ldcg(xr_p + jg);
        const float xz = __ldcg(xr_p + 256 + jg);
        const float xn = __ldcg(xr_p + 512 + jg);

        float hr, hz, hn;
        if (t == 0) {
            hr = bh0; hz = bh1; hn = bh2;   // h == 0 -> matvec is zero
        } else {
            const int ip = (t - 1) & 1;
            if (ip == 0) { MBARRIER_WAIT_PARITY(mb0, ph0);     ph0 ^= 1; }
            else         { MBARRIER_WAIT_PARITY(mb0 + 8, ph1); ph1 ^= 1; }
            if (tid == 0) MBARRIER_EXPECT_TX(mb0 + 8 * ip, 4096);  // re-arm next use

            float2 s0[4], s1[4], s2[4];
#pragma unroll
            for (int b = 0; b < 4; ++b) {
                s0[b] = make_float2(0.f, 0.f);
                s1[b] = make_float2(0.f, 0.f);
                s2[b] = make_float2(0.f, 0.f);
            }
#pragma unroll 4
            for (int i = 0; i < 16; ++i) {
                const int f4 = i * 4 + kq;
                float4 wv0 = __ldg(w0 + f4);       // L1-resident across steps
                float4 wv1 = __ldg(w1 + f4);
                float4 wv2 = __ldg(w2 + f4);
#pragma unroll
                for (int b = 0; b < 4; ++b) {
                    float4 hv = *(const float4*)&hbuf[ip][b][f4 << 2];
                    s0[b] = ffma2(make_float2(wv0.x, wv0.y), make_float2(hv.x, hv.y), s0[b]);
                    s0[b] = ffma2(make_float2(wv0.z, wv0.w), make_float2(hv.z, hv.w), s0[b]);
                    s1[b] = ffma2(make_float2(wv1.x, wv1.y), make_float2(hv.x, hv.y), s1[b]);
                    s1[b] = ffma2(make_float2(wv1.z, wv1.w), make_float2(hv.z, hv.w), s1[b]);
                    s2[b] = ffma2(make_float2(wv2.x, wv2.y), make_float2(hv.x, hv.y), s2[b]);
                    s2[b] = ffma2(make_float2(wv2.z, wv2.w), make_float2(hv.z, hv.w), s2[b]);
                }
            }
            // reduce the 4 k-quarters across the quad; every lane ends with full sums
#pragma unroll
            for (int b = 0; b < 4; ++b) {
#pragma unroll
                for (int m = 1; m <= 2; m <<= 1) {
                    s0[b].x += __shfl_xor_sync(0xffffffffu, s0[b].x, m);
                    s0[b].y += __shfl_xor_sync(0xffffffffu, s0[b].y, m);
                    s1[b].x += __shfl_xor_sync(0xffffffffu, s1[b].x, m);
                    s1[b].y += __shfl_xor_sync(0xffffffffu, s1[b].y, m);
                    s2[b].x += __shfl_xor_sync(0xffffffffu, s2[b].x, m);
                    s2[b].y += __shfl_xor_sync(0xffffffffu, s2[b].y, m);
                }
            }
            float2 t0 = s0[0], t1 = s1[0], t2 = s2[0];
            if (kq == 1) { t0 = s0[1]; t1 = s1[1]; t2 = s2[1]; }
            else if (kq == 2) { t0 = s0[2]; t1 = s1[2]; t2 = s2[2]; }
            else if (kq == 3) { t0 = s0[3]; t1 = s1[3]; t2 = s2[3]; }
            hr = t0.x + t0.y + bh0;
            hz = t1.x + t1.y + bh1;
            hn = t2.x + t2.y + bh2;
        }

        const float r = sigm(xr + hr);
        const float z = sigm(xz + hz);
        const float n = tanhf(xn + r * hn);
        const float hnew = (1.f - z) * n + z * hprev;
        hprev = hnew;

        __stcg(&seq[((size_t)(b0 + kq) * TT + t) * HH + jg], hnew);
        if (hlast != nullptr && t == TT - 1)
            __stcg(&hlast[(size_t)(b0 + kq) * HH + jg], hnew);

        // broadcast my h value to all 4 CTAs' buffer[t&1]
        const uint32_t po = (uint32_t)(t & 1);
        const uint32_t uval = __float_as_uint(hnew);
#pragma unroll
        for (int r2 = 0; r2 < 4; ++r2)
            ST_ASYNC_B32(rh[r2] + po * 4096u, uval, rm[r2] + po * 8u);
    }

    // drain: h(63) landed in mbar[1]'s final phase; consume it so no st.async
    // targets our smem after exit, then cluster-sync out.
    MBARRIER_WAIT_PARITY(mb0 + 8, ph1);
    CLUSTER_SYNC();
}

// ---------------- attention (CTA per batch) ----------------
#define AT_SMEM_FLOATS (2 * 64 * 260 + 64 * 68 + 256)
#define AT_SMEM_BYTES  (AT_SMEM_FLOATS * 4)

__global__ void __launch_bounds__(256, 1)
attn_k(const float* __restrict__ Wa, const float* __restrict__ Ua,
       const float* __restrict__ enc, const float* __restrict__ va,
       float* __restrict__ ctx)
{
    extern __shared__ float sm[];
    float* WA = sm;
    float* UA = sm + 64 * 260;
    float* ES = sm + 2 * 64 * 260;
    float* VS = ES + 64 * 68;

    const int b = blockIdx.x;
    const int tid = threadIdx.x;
    const float* waB = Wa + (size_t)b * 64 * 256;
    const float* uaB = Ua + (size_t)b * 64 * 256;

    for (int idx = tid; idx < 4096; idx += 256) {
        int k = idx >> 6, h4 = idx & 63;
        float4 w4 = __ldg((const float4*)waB + idx);
        *(float4*)&WA[k * 260 + ((h4 ^ (k & 7)) << 2)] = w4;   // xor swizzle
        float4 u4 = __ldg((const float4*)uaB + idx);
        *(float4*)&UA[k * 260 + (h4 << 2)] = u4;
    }
    if (tid < 64) *(float4*)&VS[tid * 4] = __ldg((const float4*)va + tid);
    __syncthreads();

    const int tq = tid >> 3, kq = tid & 7;
    const int t0 = tq * 2;
    float e0[8], e1[8];
#pragma unroll
    for (int i = 0; i < 8; ++i) { e0[i] = 0.f; e1[i] = 0.f; }

    for (int h4 = 0; h4 < 64; ++h4) {
        float4 v4 = *(const float4*)&VS[h4 * 4];
        float4 uA = *(const float4*)&UA[t0 * 260 + h4 * 4];
        float4 uB = *(const float4*)&UA[(t0 + 1) * 260 + h4 * 4];
#pragma unroll
        for (int i = 0; i < 8; ++i) {
            int k = i * 8 + kq;
            float4 w4 = *(const float4*)&WA[k * 260 + ((h4 ^ kq) << 2)];
            e0[i] += tanha(w4.x + uA.x) * v4.x + tanha(w4.y + uA.y) * v4.y
                   + tanha(w4.z + uA.z) * v4.z + tanha(w4.w + uA.w) * v4.w;
            e1[i] += tanha(w4.x + uB.x) * v4.x + tanha(w4.y + uB.y) * v4.y
                   + tanha(w4.z + uB.z) * v4.z + tanha(w4.w + uB.w) * v4.w;
        }
    }
#pragma unroll
    for (int i = 0; i < 8; ++i) {
        ES[t0 * 68 + i * 8 + kq] = e0[i];
        ES[(t0 + 1) * 68 + i * 8 + kq] = e1[i];
    }
    __syncthreads();

    const float* encB = enc + (size_t)b * 64 * 256;
    for (int idx = tid; idx < 4096; idx += 256) {
        int k = idx >> 6, h4 = idx & 63;
        *(float4*)&WA[k * 260 + (h4 << 2)] = __ldg((const float4*)encB + idx);
    }
    __syncthreads();

    if (tid < 64) {
        float* er = &ES[tid * 68];
        float mx = -1e30f;
        for (int k = 0; k < 64; ++k) mx = fmaxf(mx, er[k]);
        float s = 0.f;
        for (int k = 0; k < 64; ++k) { float e = __expf(er[k] - mx); er[k] = e; s += e; }
        float inv = 1.f / s;
        for (int k = 0; k < 64; ++k) er[k] *= inv;
    }
    __syncthreads();

    const int tq2 = tid >> 4, hq = tid & 15;
    const int tb = tq2 * 4;
    float4 cacc[4][4];
#pragma unroll
    for (int dt = 0; dt < 4; ++dt)
#pragma unroll
        for (int jj = 0; jj < 4; ++jj) cacc[dt][jj] = make_float4(0.f, 0.f, 0.f, 0.f);

    for (int k = 0; k < 64; ++k) {
        float al[4];
#pragma unroll
        for (int dt = 0; dt < 4; ++dt) al[dt] = ES[(tb + dt) * 68 + k];
        float4 ev[4];
#pragma unroll
        for (int jj = 0; jj < 4; ++jj) ev[jj] = *(const float4*)&WA[k * 260 + hq * 16 + jj * 4];
#pragma unroll
        for (int dt = 0; dt < 4; ++dt)
#pragma unroll
            for (int jj = 0; jj < 4; ++jj) cacc[dt][jj] = ffma4(al[dt], ev[jj], cacc[dt][jj]);
    }
#pragma unroll
    for (int dt = 0; dt < 4; ++dt)
#pragma unroll
        for (int jj = 0; jj < 4; ++jj)
            *(float4*)&ctx[(size_t)(b * 64 + tb + dt) * 256 + hq * 16 + jj * 4] = cacc[dt][jj];
}

// ---------------- launch ----------------
extern "C" void kernel_launch(void* const* d_in, const int* in_sizes, int n_in,
                              void* d_out, int out_size)
{
    const int*   x     = (const int*)  d_in[0];
    const float* embed = (const float*)d_in[1];
    const float* w_ih0 = (const float*)d_in[2];
    const float* w_hh0 = (const float*)d_in[3];
    const float* b_ih0 = (const float*)d_in[4];
    const float* b_hh0 = (const float*)d_in[5];
    const float* w_ih1 = (const float*)d_in[6];
    const float* w_hh1 = (const float*)d_in[7];
    const float* b_ih1 = (const float*)d_in[8];
    const float* b_hh1 = (const float*)d_in[9];
    const float* W_a   = (const float*)d_in[10];
    const float* U_a   = (const float*)d_in[11];
    const float* v_a   = (const float*)d_in[12];
    const float* fc_W  = (const float*)d_in[13];
    const float* fc_b  = (const float*)d_in[14];

    float* out = (float*)d_out;                 // logits (B,T,V) then h_last (B,H)
    float* hlast = out + (size_t)BB * TT * VV;

    float *xp, *seq, *enc, *wa, *ua, *ctx;
    cudaGetSymbolAddress((void**)&xp,  g_xp);
    cudaGetSymbolAddress((void**)&seq, g_seq);
    cudaGetSymbolAddress((void**)&enc, g_enc);
    cudaGetSymbolAddress((void**)&wa,  g_Wa);
    cudaGetSymbolAddress((void**)&ua,  g_Ua);
    cudaGetSymbolAddress((void**)&ctx, g_ctx);

    cudaFuncSetAttribute(attn_k, cudaFuncAttributeMaxDynamicSharedMemorySize, AT_SMEM_BYTES);

    const int M = BB * TT;  // 8192

    // 1. xp0 = embed[x] @ w_ih0^T + b_ih0    (gather fused)
    gemm_k<<<dim3(M / 128, G3H / 64), 256>>>(embed, HH, x, w_ih0, HH, b_ih0, xp, G3H, HH, 0);
    // 2. scan layer 0 (32 clusters x 4 CTAs)
    scan_k<<<128, 256>>>(xp, w_hh0, b_hh0, seq, nullptr);
    // 3. xp1 = seq @ w_ih1^T + b_ih1
    gemm_k<<<dim3(M / 128, G3H / 64), 256>>>(seq, HH, nullptr, w_ih1, HH, b_ih1, xp, G3H, HH, 0);
    // 4. scan layer 1 -> enc, h_last
    scan_k<<<128, 256>>>(xp, w_hh1, b_hh1, enc, hlast);
    // 5/6. attention projections
    gemm_k<<<dim3(M / 128, HH / 64), 256>>>(enc, HH, nullptr, W_a, HH, nullptr, wa, HH, HH, 0);
    gemm_k<<<dim3(M / 128, HH / 64), 256>>>(enc, HH, nullptr, U_a, HH, nullptr, ua, HH, HH, 0);
    // 7. attention -> ctx
    attn_k<<<BB, 256, AT_SMEM_BYTES>>>(wa, ua, enc, v_a, ctx);
    // 8/9. logits = enc @ fcW[:, :H]^T + b ; += ctx @ fcW[:, H:]^T
    gemm_k<<<dim3(M / 128, VV / 64), 256>>>(enc, HH, nullptr, fc_W, 2 * HH, fc_b, out, VV, HH, 0);
    gemm_k<<<dim3(M / 128, VV / 64), 256>>>(ctx, HH, nullptr, fc_W + HH, 2 * HH, nullptr, out, VV, HH, 1);
}